// round 5
// baseline (speedup 1.0000x reference)
#include <cuda_runtime.h>
#include <math_constants.h>

// Problem constants
#define BB    16
#define CC    256
#define HH    32
#define WW    32
#define EE    256
#define NE    8192
#define HW    1024
#define ROWS  16384   // B*H*W
#define KC    2304    // 9*256 im2col K

#define OUT_ELEMS   4194304
#define LOSS_OFF    4194304
#define IDX_OFF     4194305

// ---------------- device scratch ----------------
__device__ float g_ze[ROWS * EE];      // conv1 out [row][e] (bit-exact target)
__device__ float g_zf[ROWS * EE];      // post-LN  [row][e] (bit-exact target)
__device__ float g_znorm[ROWS];        // serial sum zf^2 (bit-exact)
__device__ float g_enorm[NE];          // serial sum e^2  (bit-exact)
__device__ float g_wp[KC * EE];        // conv1 weights permuted: [kk=(kh*3+kw)*256+ci][o]
__device__ float g_zq[BB * EE * HW];   // straight-through zq, NCHW
__device__ int   g_idx[ROWS];
__device__ float g_lpart[ROWS];

// ---------------- helpers ----------------
__device__ __forceinline__ float blk_sum(float v, float* sh) {
    int t = threadIdx.x, lane = t & 31, w = t >> 5;
    #pragma unroll
    for (int o = 16; o; o >>= 1) v += __shfl_down_sync(0xffffffffu, v, o);
    if (!lane) sh[w] = v;
    __syncthreads();
    if (w == 0) {
        float x = (lane < 8) ? sh[lane] : 0.f;
        #pragma unroll
        for (int o = 4; o; o >>= 1) x += __shfl_down_sync(0xffffffffu, x, o);
        if (!lane) sh[0] = x;
    }
    __syncthreads();
    float r = sh[0];
    __syncthreads();
    return r;
}

// ---------------- weight permute for conv1 ----------------
// emb_w layout [o][ci][kh][kw] -> g_wp[(kh*3+kw)*256+ci][o]
__global__ __launch_bounds__(256) void permw_kernel(const float* __restrict__ Wm) {
    int i = blockIdx.x * 256 + threadIdx.x;       // i over KC*EE
    if (i < KC * EE) {
        int o = i & 255;
        int kk = i >> 8;          // (kh*3+kw)*256 + ci
        int ci = kk & 255;
        int khw = kk >> 8;        // kh*3+kw
        g_wp[kk * 256 + o] = Wm[o * KC + ci * 9 + khw];
    }
}

// ---------------- kernel: codebook row norms, serial ascending ----------------
__global__ __launch_bounds__(256) void enorm_kernel(const float* __restrict__ cb) {
    int n = blockIdx.x * 256 + threadIdx.x;
    if (n < NE) {
        const float* r = cb + n * EE;
        float s = 0.f;
        for (int k = 0; k < EE; k++) {
            float p = __fmul_rn(r[k], r[k]);   // square rounded (separate HLO op)
            s = __fadd_rn(s, p);               // serial ascending reduce
        }
        g_enorm[n] = s;
    }
}

// ---------------- conv1: bit-exact serial-k im2col GEMM ----------------
// ze[row][o] = bias[o] + serial_{kk=0..2303} fma(x_patch[kk], wp[kk][o])
// kk order = (kh,kw) outer, ci inner  (Eigen NHWC im2col contraction order)
__global__ __launch_bounds__(256) void conv1_exact(const float* __restrict__ X,
                                                   const float* __restrict__ bias) {
    __shared__ float As[16][132];
    __shared__ float Bs[16][132];

    int t = threadIdx.x;
    int tx = t & 15, ty = t >> 4;
    int row0 = blockIdx.x * 128;
    int n0 = blockIdx.y * 128;

    float acc[8][8];
    #pragma unroll
    for (int i = 0; i < 8; i++)
        #pragma unroll
        for (int j = 0; j < 8; j++) acc[i][j] = 0.f;

    for (int k0 = 0; k0 < KC; k0 += 16) {
        #pragma unroll
        for (int e = 0; e < 8; e++) {
            int lin = t + e * 256;
            int m = lin & 127, k = lin >> 7;
            int kk = k0 + k;
            int ci = kk & 255;
            int khw = kk >> 8;
            int kh = khw / 3, kw = khw - kh * 3;
            int row = row0 + m;
            int b = row >> 10;
            int hw = row & 1023;
            int h = (hw >> 5) + kh - 1;
            int w = (hw & 31) + kw - 1;
            float v = 0.f;
            if ((unsigned)h < 32u && (unsigned)w < 32u)
                v = X[((b * 256 + ci) << 10) + (h << 5) + w];
            As[k][m] = v;
        }
        #pragma unroll
        for (int e = 0; e < 8; e++) {
            int lin = t + e * 256;
            int n = lin & 127, k = lin >> 7;
            Bs[k][n0 ? n : n] = g_wp[(k0 + k) * 256 + n0 + n];
        }
        __syncthreads();
        #pragma unroll
        for (int k = 0; k < 16; k++) {      // ascending k: serial fma chain per acc
            float a[8], b2[8];
            #pragma unroll
            for (int i = 0; i < 8; i++) a[i] = As[k][ty * 8 + i];
            #pragma unroll
            for (int j = 0; j < 8; j++) b2[j] = Bs[k][tx * 8 + j];
            #pragma unroll
            for (int i = 0; i < 8; i++)
                #pragma unroll
                for (int j = 0; j < 8; j++)
                    acc[i][j] = __fmaf_rn(a[i], b2[j], acc[i][j]);
        }
        __syncthreads();
    }

    #pragma unroll
    for (int i = 0; i < 8; i++) {
        int row = row0 + ty * 8 + i;
        #pragma unroll
        for (int j = 0; j < 8; j++) {
            int n = n0 + tx * 8 + j;
            g_ze[row * 256 + n] = __fadd_rn(acc[i][j], bias[n]);
        }
    }
}

// ---------------- LayerNorm, serial-scalar reductions (XLA CPU semantics) ----------------
// one thread per row
__global__ __launch_bounds__(256) void ln_exact(const float* __restrict__ g,
                                                const float* __restrict__ be) {
    int row = blockIdx.x * 256 + threadIdx.x;
    if (row >= ROWS) return;
    const float* x = g_ze + row * 256;
    float s = 0.f;
    for (int k = 0; k < 256; k++) s = __fadd_rn(s, x[k]);
    float mu = __fmul_rn(s, 1.f / 256.f);            // /256 exact (power of two)
    float s2 = 0.f;
    for (int k = 0; k < 256; k++) {
        float tq = __fsub_rn(x[k], mu);
        s2 = __fadd_rn(s2, __fmul_rn(tq, tq));
    }
    float var = __fmul_rn(s2, 1.f / 256.f);
    float rs = __fdiv_rn(1.0f, __fsqrt_rn(__fadd_rn(var, 1e-5f)));
    float zn = 0.f;
    float* zf = g_zf + row * 256;
    for (int k = 0; k < 256; k++) {
        float tq = __fsub_rn(x[k], mu);
        float a = __fmul_rn(tq, rs);
        float v = __fadd_rn(__fmul_rn(a, g[k]), be[k]);   // ((x-mu)*rs)*g + b
        zf[k] = v;
        zn = __fadd_rn(zn, __fmul_rn(v, v));              // serial sum of rounded zf^2
    }
    g_znorm[row] = zn;
}

// ---------------- distance GEMM + bucketed argmin ----------------
// d_n = RN( RN(znorm + enorm_n) - 2*dot_n ),  dot_n = serial ascending fp32 fma chain
// winner = lowest index among grid-tied minima (monotone rounding => first-min)
__global__ __launch_bounds__(256) void dist_exact(const float* __restrict__ cb) {
    __shared__ float As[16][132];
    __shared__ float Bs[16][132];
    __shared__ float rv[128][17];
    __shared__ int   ri[128][16];
    __shared__ float zns[128];

    int t = threadIdx.x;
    int tx = t & 15, ty = t >> 4;
    int row0 = blockIdx.x * 128;

    if (t < 128) zns[t] = g_znorm[row0 + t];

    float best[8];
    int bidx[8];
    #pragma unroll
    for (int i = 0; i < 8; i++) { best[i] = CUDART_INF_F; bidx[i] = 0x7fffffff; }
    __syncthreads();

    for (int n0 = 0; n0 < NE; n0 += 128) {
        float acc[8][8];
        #pragma unroll
        for (int i = 0; i < 8; i++)
            #pragma unroll
            for (int j = 0; j < 8; j++) acc[i][j] = 0.f;

        #pragma unroll
        for (int k0 = 0; k0 < 256; k0 += 16) {
            #pragma unroll
            for (int e = 0; e < 8; e++) {
                int lin = t + e * 256;
                int k = lin & 15, m = lin >> 4;
                As[k][m] = g_zf[(row0 + m) * 256 + k0 + k];
            }
            #pragma unroll
            for (int e = 0; e < 8; e++) {
                int lin = t + e * 256;
                int k = lin & 15, n = lin >> 4;
                Bs[k][n] = cb[(n0 + n) * 256 + k0 + k];
            }
            __syncthreads();
            #pragma unroll
            for (int k = 0; k < 16; k++) {   // ascending: serial fma chain per acc
                float a[8], b2[8];
                #pragma unroll
                for (int i = 0; i < 8; i++) a[i] = As[k][ty * 8 + i];
                #pragma unroll
                for (int j = 0; j < 8; j++) b2[j] = Bs[k][tx * 8 + j];
                #pragma unroll
                for (int i = 0; i < 8; i++)
                    #pragma unroll
                    for (int j = 0; j < 8; j++)
                        acc[i][j] = __fmaf_rn(a[i], b2[j], acc[i][j]);
            }
            __syncthreads();
        }

        #pragma unroll
        for (int j = 0; j < 8; j++) {        // n ascending within thread
            int n = n0 + tx * 8 + j;
            float en = g_enorm[n];
            #pragma unroll
            for (int i = 0; i < 8; i++) {
                float S = __fadd_rn(zns[ty * 8 + i], en);          // znorm + enorm (RN)
                float d = __fsub_rn(S, __fmul_rn(2.0f, acc[i][j])); // - 2*dot   (RN)
                if (d < best[i] || (d == best[i] && n < bidx[i])) { best[i] = d; bidx[i] = n; }
            }
        }
    }

    #pragma unroll
    for (int i = 0; i < 8; i++) {
        rv[ty * 8 + i][tx] = best[i];
        ri[ty * 8 + i][tx] = bidx[i];
    }
    __syncthreads();
    if (t < 128) {
        float bv = rv[t][0];
        int bi = ri[t][0];
        #pragma unroll
        for (int x = 1; x < 16; x++) {
            float v = rv[t][x];
            int ix = ri[t][x];
            if (v < bv || (v == bv && ix < bi)) { bv = v; bi = ix; }
        }
        g_idx[row0 + t] = bi;
    }
}

// ---------------- gather + straight-through + loss partials ----------------
__global__ __launch_bounds__(256) void gather_kernel(const float* __restrict__ cb) {
    __shared__ float sh[32];
    int row = blockIdx.x, t = threadIdx.x;
    int id = g_idx[row];
    float e = cb[id * 256 + t];
    float z = g_ze[row * 256 + t];
    float d = __fsub_rn(e, z);          // z_q - ze   (RN)
    float zq = __fadd_rn(z, d);         // ze + (z_q - ze)  (RN) — straight-through bits
    int b = row >> 10, hw = row & 1023;
    g_zq[((b * 256 + t) << 10) + hw] = zq;
    float s = blk_sum(__fmul_rn(d, d), sh);
    if (t == 0) g_lpart[row] = s;
}

// ---------------- conv2 (tolerance 1e-3 — plain fp32 tiled GEMM) ----------------
__global__ __launch_bounds__(256) void conv2_gemm(const float* __restrict__ Wm,
                                                  const float* __restrict__ bias,
                                                  float* __restrict__ outNCHW) {
    __shared__ float As[16][132];
    __shared__ float Bs[16][132];
    int t = threadIdx.x;
    int tx = t & 15, ty = t >> 4;
    int row0 = blockIdx.x * 128;
    int n0 = blockIdx.y * 128;

    float acc[8][8];
    #pragma unroll
    for (int i = 0; i < 8; i++)
        #pragma unroll
        for (int j = 0; j < 8; j++) acc[i][j] = 0.f;

    for (int k0 = 0; k0 < KC; k0 += 16) {
        #pragma unroll
        for (int e = 0; e < 8; e++) {
            int lin = t + e * 256;
            int m = lin & 127, k = lin >> 7;
            int kk = k0 + k;
            int ci = kk / 9;
            int r9 = kk - ci * 9;
            int kh = r9 / 3, kw = r9 - kh * 3;
            int row = row0 + m;
            int b = row >> 10;
            int hw = row & 1023;
            int h = (hw >> 5) + kh - 1;
            int w = (hw & 31) + kw - 1;
            float v = 0.f;
            if ((unsigned)h < 32u && (unsigned)w < 32u)
                v = g_zq[((b * 256 + ci) << 10) + (h << 5) + w];
            As[k][m] = v;
        }
        #pragma unroll
        for (int e = 0; e < 8; e++) {
            int lin = t + e * 256;
            int k = lin & 15, n = lin >> 4;
            Bs[k][n] = Wm[(n0 + n) * KC + k0 + k];
        }
        __syncthreads();
        #pragma unroll
        for (int k = 0; k < 16; k++) {
            float a[8], b2[8];
            #pragma unroll
            for (int i = 0; i < 8; i++) a[i] = As[k][ty * 8 + i];
            #pragma unroll
            for (int j = 0; j < 8; j++) b2[j] = Bs[k][tx * 8 + j];
            #pragma unroll
            for (int i = 0; i < 8; i++)
                #pragma unroll
                for (int j = 0; j < 8; j++)
                    acc[i][j] = __fmaf_rn(a[i], b2[j], acc[i][j]);
        }
        __syncthreads();
    }

    #pragma unroll
    for (int i = 0; i < 8; i++) {
        int row = row0 + ty * 8 + i;
        int b = row >> 10;
        int hw = row & 1023;
        #pragma unroll
        for (int j = 0; j < 8; j++) {
            int n = n0 + tx * 8 + j;
            outNCHW[((b * 256 + n) << 10) + hw] = __fadd_rn(acc[i][j], bias[n]);
        }
    }
}

// ---------------- finalize: loss + idx ----------------
__global__ __launch_bounds__(256) void finalize_kernel(float* __restrict__ out, int out_size) {
    __shared__ float sh[32];
    int gidx = blockIdx.x * blockDim.x + threadIdx.x;
    if (gidx < ROWS && IDX_OFF + gidx < out_size)
        out[IDX_OFF + gidx] = (float)g_idx[gidx];
    if (blockIdx.x == 0) {
        float s = 0.f;
        for (int k = threadIdx.x; k < ROWS; k += 256) s += g_lpart[k];
        float tot = blk_sum(s, sh);
        if (threadIdx.x == 0 && LOSS_OFF < out_size)
            out[LOSS_OFF] = 1.25f * tot / (float)OUT_ELEMS;
    }
}

// ---------------- launcher ----------------
extern "C" void kernel_launch(void* const* d_in, const int* in_sizes, int n_in,
                              void* d_out, int out_size) {
    (void)in_sizes; (void)n_in;
    const float* z       = (const float*)d_in[0];
    const float* emb_w   = (const float*)d_in[1];
    const float* emb_b   = (const float*)d_in[2];
    const float* ln_g    = (const float*)d_in[3];
    const float* ln_b    = (const float*)d_in[4];
    const float* cb      = (const float*)d_in[5];
    const float* unemb_w = (const float*)d_in[6];
    const float* unemb_b = (const float*)d_in[7];
    float* out = (float*)d_out;

    permw_kernel<<<(KC * EE + 255) / 256, 256>>>(emb_w);
    enorm_kernel<<<(NE + 255) / 256, 256>>>(cb);
    conv1_exact<<<dim3(ROWS / 128, 2), 256>>>(z, emb_b);
    ln_exact<<<ROWS / 256, 256>>>(ln_g, ln_b);
    dist_exact<<<ROWS / 128, 256>>>(cb);
    gather_kernel<<<ROWS, 256>>>(cb);
    conv2_gemm<<<dim3(ROWS / 128, 2), 256>>>(unemb_w, unemb_b, out);
    finalize_kernel<<<(ROWS + 255) / 256, 256>>>(out, out_size);
}

// round 10
// speedup vs baseline: 1.2265x; 1.2265x over previous
#include <cuda_runtime.h>
#include <math_constants.h>

// Problem constants
#define BB    16
#define CC    256
#define HH    32
#define WW    32
#define EE    256
#define NE    8192
#define HW    1024
#define ROWS  16384   // B*H*W
#define KC    2304    // 9*256 im2col K

#define OUT_ELEMS   4194304
#define LOSS_OFF    4194304
#define IDX_OFF     4194305

#define GBLK  512               // gather blocks (ROWS/32)

// ---------------- device scratch ----------------
__device__ float g_ze[ROWS * EE];      // conv1 out [row][e] (bit-exact)
__device__ float g_zf[ROWS * EE];      // post-LN  [row][e] (bit-exact)
__device__ float g_znorm[ROWS];        // serial sum zf^2
__device__ float g_enorm[NE];          // serial sum e^2
__device__ float g_wp[KC * EE];        // conv1 W permuted: [(khw*256+ci)][o]
__device__ float g_zq[BB * EE * HW];   // straight-through zq, NCHW
__device__ int   g_idx[ROWS];
__device__ float g_lpart[GBLK];

// ---------------- helpers ----------------
__device__ __forceinline__ float blk_sum(float v, float* sh) {
    int t = threadIdx.x, lane = t & 31, w = t >> 5;
    #pragma unroll
    for (int o = 16; o; o >>= 1) v += __shfl_down_sync(0xffffffffu, v, o);
    if (!lane) sh[w] = v;
    __syncthreads();
    if (w == 0) {
        float x = (lane < 8) ? sh[lane] : 0.f;
        #pragma unroll
        for (int o = 4; o; o >>= 1) x += __shfl_down_sync(0xffffffffu, x, o);
        if (!lane) sh[0] = x;
    }
    __syncthreads();
    float r = sh[0];
    __syncthreads();
    return r;
}

// ---------------- weight permute: [o][ci][kh][kw] -> [(khw*256+ci)][o] ----------------
// NOTE: writes the __device__ global directly — device symbols must never be
// passed as kernel arguments from host code (host shadow symbol != device ptr).
__global__ __launch_bounds__(256) void permw_kernel(const float* __restrict__ Wm) {
    int i = blockIdx.x * 256 + threadIdx.x;       // over KC*EE
    if (i < KC * EE) {
        int o = i & 255;
        int kk = i >> 8;          // (khw)*256 + ci
        int ci = kk & 255;
        int khw = kk >> 8;
        g_wp[kk * 256 + o] = Wm[o * KC + ci * 9 + khw];
    }
}

// ---------------- enorm3: static-smem staged, serial ascending per row ----------------
#define LN_STR 260
__global__ __launch_bounds__(256) void enorm3_kernel(const float* __restrict__ cb) {
    __shared__ float ls[32 * LN_STR];              // 33.3 KB static
    int t = threadIdx.x;
    int r0 = blockIdx.x * 32;
    const float4* src = (const float4*)(cb + r0 * 256);
    #pragma unroll
    for (int e = 0; e < 8; e++) {
        int lin = t + (e << 8);                    // 0..2047
        float4 v = src[lin];
        int row = lin >> 6;
        int kq = (lin & 63) << 2;
        *(float4*)&ls[row * LN_STR + kq] = v;
    }
    __syncthreads();
    if (t < 32) {
        const float* x = ls + t * LN_STR;
        float s = 0.f;
        for (int k = 0; k < 256; k++)
            s = __fadd_rn(s, __fmul_rn(x[k], x[k]));
        g_enorm[r0 + t] = s;
    }
}

// ---------------- conv1: bit-exact serial-k im2col GEMM (R4-proven) ----------------
__global__ __launch_bounds__(256) void conv1_exact(const float* __restrict__ X,
                                                   const float* __restrict__ bias) {
    __shared__ float As[16][132];
    __shared__ float Bs[16][132];

    int t = threadIdx.x;
    int tx = t & 15, ty = t >> 4;
    int row0 = blockIdx.x * 128;
    int n0 = blockIdx.y * 128;

    float acc[8][8];
    #pragma unroll
    for (int i = 0; i < 8; i++)
        #pragma unroll
        for (int j = 0; j < 8; j++) acc[i][j] = 0.f;

    for (int k0 = 0; k0 < KC; k0 += 16) {
        #pragma unroll
        for (int e = 0; e < 8; e++) {
            int lin = t + e * 256;
            int m = lin & 127, k = lin >> 7;
            int kk = k0 + k;
            int ci = kk & 255;
            int khw = kk >> 8;
            int kh = khw / 3, kw = khw - kh * 3;
            int row = row0 + m;
            int b = row >> 10;
            int hw = row & 1023;
            int h = (hw >> 5) + kh - 1;
            int w = (hw & 31) + kw - 1;
            float v = 0.f;
            if ((unsigned)h < 32u && (unsigned)w < 32u)
                v = X[((b * 256 + ci) << 10) + (h << 5) + w];
            As[k][m] = v;
            Bs[k][m] = g_wp[(k0 + k) * 256 + n0 + m];
        }
        __syncthreads();
        #pragma unroll
        for (int k = 0; k < 16; k++) {
            float a[8], b2[8];
            #pragma unroll
            for (int i = 0; i < 8; i++) a[i] = As[k][ty * 8 + i];
            #pragma unroll
            for (int j = 0; j < 8; j++) b2[j] = Bs[k][tx * 8 + j];
            #pragma unroll
            for (int i = 0; i < 8; i++)
                #pragma unroll
                for (int j = 0; j < 8; j++)
                    acc[i][j] = __fmaf_rn(a[i], b2[j], acc[i][j]);
        }
        __syncthreads();
    }

    #pragma unroll
    for (int i = 0; i < 8; i++) {
        int row = row0 + ty * 8 + i;
        #pragma unroll
        for (int j = 0; j < 8; j++) {
            int n = n0 + tx * 8 + j;
            g_ze[row * 256 + n] = __fadd_rn(acc[i][j], bias[n]);
        }
    }
}

// ---------------- ln3: static-smem staged, serial-scalar per row ----------------
__global__ __launch_bounds__(256) void ln3_kernel(const float* __restrict__ g,
                                                  const float* __restrict__ be) {
    __shared__ float ls[32 * LN_STR];              // 33.3 KB static
    __shared__ float gg[256], bb[256];
    int t = threadIdx.x;
    int r0 = blockIdx.x * 32;
    gg[t] = g[t];
    bb[t] = be[t];
    const float4* src = (const float4*)(g_ze + r0 * 256);
    #pragma unroll
    for (int e = 0; e < 8; e++) {
        int lin = t + (e << 8);
        float4 v = src[lin];
        int row = lin >> 6;
        int kq = (lin & 63) << 2;
        *(float4*)&ls[row * LN_STR + kq] = v;
    }
    __syncthreads();
    if (t < 32) {
        float* x = ls + t * LN_STR;
        float s = 0.f;
        for (int k = 0; k < 256; k++) s = __fadd_rn(s, x[k]);
        float mu = __fmul_rn(s, 1.f / 256.f);
        float s2 = 0.f;
        for (int k = 0; k < 256; k++) {
            float tq = __fsub_rn(x[k], mu);
            s2 = __fadd_rn(s2, __fmul_rn(tq, tq));
        }
        float var = __fmul_rn(s2, 1.f / 256.f);
        float rs = __fdiv_rn(1.0f, __fsqrt_rn(__fadd_rn(var, 1e-5f)));
        float zn = 0.f;
        for (int k = 0; k < 256; k++) {
            float tq = __fsub_rn(x[k], mu);
            float a = __fmul_rn(tq, rs);
            float v = __fadd_rn(__fmul_rn(a, gg[k]), bb[k]);
            x[k] = v;                                    // in-place
            zn = __fadd_rn(zn, __fmul_rn(v, v));
        }
        g_znorm[r0 + t] = zn;
    }
    __syncthreads();
    float4* dst = (float4*)(g_zf + r0 * 256);
    #pragma unroll
    for (int e = 0; e < 8; e++) {
        int lin = t + (e << 8);
        int row = lin >> 6;
        int kq = (lin & 63) << 2;
        dst[lin] = *(const float4*)&ls[row * LN_STR + kq];
    }
}

// ---------------- dist_v4: 64-row blocks, static smem, exact serial-k chains ----------------
// d_n = RN( RN(znorm + enorm_n) - 2*dot_n ), dot = serial ascending fma over k.
__global__ __launch_bounds__(256) void dist_v4(const float* __restrict__ cb) {
    __shared__ float As[16][68];      // A chunk: [k][m], m<64   (4.4 KB)
    __shared__ float Bs[16][132];     // B chunk: [k][n], n<128  (8.4 KB)
    __shared__ float rv[64][17];
    __shared__ int   ri[64][16];
    __shared__ float zns[64];

    int t = threadIdx.x;
    int tx = t & 15, ty = t >> 4;
    int row0 = blockIdx.x * 64;

    if (t < 64) zns[t] = g_znorm[row0 + t];

    int kk = t & 15;      // k within chunk (loader)
    int ml = t >> 4;      // base row / n (loader)

    float best[4];
    int bidx[4];
    #pragma unroll
    for (int i = 0; i < 4; i++) { best[i] = CUDART_INF_F; bidx[i] = 0x7fffffff; }

    for (int n0 = 0; n0 < NE; n0 += 128) {
        float acc[4][8];
        #pragma unroll
        for (int i = 0; i < 4; i++)
            #pragma unroll
            for (int j = 0; j < 8; j++) acc[i][j] = 0.f;

        #pragma unroll 1
        for (int k0 = 0; k0 < 256; k0 += 16) {
            // A chunk: 4 elems/thread
            #pragma unroll
            for (int e = 0; e < 4; e++) {
                int m = ml + e * 16;
                As[kk][m] = g_zf[(row0 + m) * 256 + k0 + kk];
            }
            // B chunk: 8 elems/thread
            #pragma unroll
            for (int e = 0; e < 8; e++) {
                int n = ml + e * 16;
                Bs[kk][n] = cb[(n0 + n) * 256 + k0 + kk];
            }
            __syncthreads();
            #pragma unroll
            for (int k = 0; k < 16; k++) {           // k ascending: serial fma chain
                float a[4], b2[8];
                #pragma unroll
                for (int i = 0; i < 4; i++) a[i] = As[k][ty * 4 + i];
                #pragma unroll
                for (int j = 0; j < 8; j++) b2[j] = Bs[k][tx * 8 + j];
                #pragma unroll
                for (int i = 0; i < 4; i++)
                    #pragma unroll
                    for (int j = 0; j < 8; j++)
                        acc[i][j] = __fmaf_rn(a[i], b2[j], acc[i][j]);
            }
            __syncthreads();
        }

        // argmin epilogue: n ascending within thread; strict < keeps lowest index
        #pragma unroll
        for (int j = 0; j < 8; j++) {
            int n = n0 + tx * 8 + j;
            float en = g_enorm[n];
            #pragma unroll
            for (int i = 0; i < 4; i++) {
                float S = __fadd_rn(zns[ty * 4 + i], en);
                float d = __fsub_rn(S, __fmul_rn(2.0f, acc[i][j]));
                if (d < best[i]) { best[i] = d; bidx[i] = n; }
            }
        }
    }

    #pragma unroll
    for (int i = 0; i < 4; i++) {
        rv[ty * 4 + i][tx] = best[i];
        ri[ty * 4 + i][tx] = bidx[i];
    }
    __syncthreads();
    if (t < 64) {
        float bv = rv[t][0];
        int bi = ri[t][0];
        #pragma unroll
        for (int x = 1; x < 16; x++) {
            float v = rv[t][x];
            int ix = ri[t][x];
            if (v < bv || (v == bv && ix < bi)) { bv = v; bi = ix; }
        }
        g_idx[row0 + t] = bi;
    }
}

// ---------------- gather2: coalesced straight-through + loss partials ----------------
__global__ __launch_bounds__(256) void gather2_kernel(const float* __restrict__ cb) {
    __shared__ float sq[256][33];
    __shared__ int sid[32];
    __shared__ float sh[32];
    int t = threadIdx.x;
    int r0 = blockIdx.x * 32;
    if (t < 32) sid[t] = g_idx[r0 + t];
    __syncthreads();
    float local = 0.f;
    #pragma unroll 4
    for (int i = 0; i < 32; i++) {
        float e = cb[sid[i] * 256 + t];
        float z = g_ze[(r0 + i) * 256 + t];
        float d = __fsub_rn(e, z);
        sq[t][i] = __fadd_rn(z, d);              // straight-through bits
        local += d * d;                          // scalar loss: tolerance ok
    }
    __syncthreads();
    int b = r0 >> 10, hw0 = r0 & 1023;
    int w = t >> 5, lane = t & 31;
    #pragma unroll 4
    for (int eb = 0; eb < 32; eb++) {
        int e = eb * 8 + w;
        g_zq[((b * 256 + e) << 10) + hw0 + lane] = sq[e][lane];
    }
    float s = blk_sum(local, sh);
    if (t == 0) g_lpart[blockIdx.x] = s;
}

// ---------------- conv2 (R4-proven, verbatim) ----------------
__global__ __launch_bounds__(256) void conv2_gemm(const float* __restrict__ Wm,
                                                  const float* __restrict__ bias,
                                                  float* __restrict__ outNCHW) {
    __shared__ float As[16][132];
    __shared__ float Bs[16][132];
    int t = threadIdx.x;
    int tx = t & 15, ty = t >> 4;
    int row0 = blockIdx.x * 128;
    int n0 = blockIdx.y * 128;

    float acc[8][8];
    #pragma unroll
    for (int i = 0; i < 8; i++)
        #pragma unroll
        for (int j = 0; j < 8; j++) acc[i][j] = 0.f;

    for (int k0 = 0; k0 < KC; k0 += 16) {
        #pragma unroll
        for (int e = 0; e < 8; e++) {
            int lin = t + e * 256;
            int m = lin & 127, k = lin >> 7;
            int kk = k0 + k;
            int ci = kk / 9;
            int r9 = kk - ci * 9;
            int kh = r9 / 3, kw = r9 - kh * 3;
            int row = row0 + m;
            int b = row >> 10;
            int hw = row & 1023;
            int h = (hw >> 5) + kh - 1;
            int w = (hw & 31) + kw - 1;
            float v = 0.f;
            if ((unsigned)h < 32u && (unsigned)w < 32u)
                v = g_zq[((b * 256 + ci) << 10) + (h << 5) + w];
            As[k][m] = v;
        }
        #pragma unroll
        for (int e = 0; e < 8; e++) {
            int lin = t + e * 256;
            int k = lin & 15, n = lin >> 4;
            Bs[k][n] = Wm[(n0 + n) * KC + k0 + k];
        }
        __syncthreads();
        #pragma unroll
        for (int k = 0; k < 16; k++) {
            float a[8], b2[8];
            #pragma unroll
            for (int i = 0; i < 8; i++) a[i] = As[k][ty * 8 + i];
            #pragma unroll
            for (int j = 0; j < 8; j++) b2[j] = Bs[k][tx * 8 + j];
            #pragma unroll
            for (int i = 0; i < 8; i++)
                #pragma unroll
                for (int j = 0; j < 8; j++)
                    acc[i][j] = __fmaf_rn(a[i], b2[j], acc[i][j]);
        }
        __syncthreads();
    }

    #pragma unroll
    for (int i = 0; i < 8; i++) {
        int row = row0 + ty * 8 + i;
        int b = row >> 10;
        int hw = row & 1023;
        #pragma unroll
        for (int j = 0; j < 8; j++) {
            int n = n0 + tx * 8 + j;
            outNCHW[((b * 256 + n) << 10) + hw] = __fadd_rn(acc[i][j], bias[n]);
        }
    }
}

// ---------------- finalize: loss + idx ----------------
__global__ __launch_bounds__(256) void finalize_kernel(float* __restrict__ out, int out_size) {
    __shared__ float sh[32];
    int gidx = blockIdx.x * blockDim.x + threadIdx.x;
    if (gidx < ROWS && IDX_OFF + gidx < out_size)
        out[IDX_OFF + gidx] = (float)g_idx[gidx];
    if (blockIdx.x == 0) {
        float s = 0.f;
        for (int k = threadIdx.x; k < GBLK; k += 256) s += g_lpart[k];
        float tot = blk_sum(s, sh);
        if (threadIdx.x == 0 && LOSS_OFF < out_size)
            out[LOSS_OFF] = 1.25f * tot / (float)OUT_ELEMS;
    }
}

// ---------------- launcher ----------------
extern "C" void kernel_launch(void* const* d_in, const int* in_sizes, int n_in,
                              void* d_out, int out_size) {
    (void)in_sizes; (void)n_in;
    const float* z       = (const float*)d_in[0];
    const float* emb_w   = (const float*)d_in[1];
    const float* emb_b   = (const float*)d_in[2];
    const float* ln_g    = (const float*)d_in[3];
    const float* ln_b    = (const float*)d_in[4];
    const float* cb      = (const float*)d_in[5];
    const float* unemb_w = (const float*)d_in[6];
    const float* unemb_b = (const float*)d_in[7];
    float* out = (float*)d_out;

    permw_kernel<<<(KC * EE + 255) / 256, 256>>>(emb_w);
    enorm3_kernel<<<NE / 32, 256>>>(cb);
    conv1_exact<<<dim3(ROWS / 128, 2), 256>>>(z, emb_b);                  // -> g_ze
    ln3_kernel<<<ROWS / 32, 256>>>(ln_g, ln_b);                           // -> g_zf, g_znorm
    dist_v4<<<ROWS / 64, 256>>>(cb);                                      // -> g_idx
    gather2_kernel<<<GBLK, 256>>>(cb);                                    // -> g_zq, g_lpart
    conv2_gemm<<<dim3(ROWS / 128, 2), 256>>>(unemb_w, unemb_b, out);      // -> out
    finalize_kernel<<<ROWS / 256, 256>>>(out, out_size);
}

// round 11
// speedup vs baseline: 1.6719x; 1.3631x over previous
#include <cuda_runtime.h>
#include <math_constants.h>

// Problem constants
#define BB    16
#define CC    256
#define HH    32
#define WW    32
#define EE    256
#define NE    8192
#define HW    1024
#define ROWS  16384   // B*H*W
#define KC    2304    // 9*256 im2col K

#define OUT_ELEMS   4194304
#define LOSS_OFF    4194304
#define IDX_OFF     4194305

#define GBLK  512               // gather blocks (ROWS/32)

// ---------------- device scratch ----------------
__device__ float g_ze[ROWS * EE];      // conv1 out [row][e] (bit-exact)
__device__ float g_zf[ROWS * EE];      // post-LN  [row][e] (bit-exact)
__device__ float g_znorm[ROWS];        // serial sum zf^2
__device__ float g_enorm[NE];          // serial sum e^2
__device__ float g_wp[KC * EE];        // conv1 W permuted: [(khw*256+ci)][o]
__device__ float g_zq[BB * EE * HW];   // straight-through zq, NCHW
__device__ int   g_idx[ROWS];
__device__ float g_lpart[GBLK];
__device__ float g_cv[32 * ROWS];      // argmin candidates: value  [cand][row]
__device__ int   g_ci[32 * ROWS];      // argmin candidates: index  [cand][row]

// ---------------- helpers ----------------
__device__ __forceinline__ float blk_sum(float v, float* sh) {
    int t = threadIdx.x, lane = t & 31, w = t >> 5;
    #pragma unroll
    for (int o = 16; o; o >>= 1) v += __shfl_down_sync(0xffffffffu, v, o);
    if (!lane) sh[w] = v;
    __syncthreads();
    if (w == 0) {
        float x = (lane < 8) ? sh[lane] : 0.f;
        #pragma unroll
        for (int o = 4; o; o >>= 1) x += __shfl_down_sync(0xffffffffu, x, o);
        if (!lane) sh[0] = x;
    }
    __syncthreads();
    float r = sh[0];
    __syncthreads();
    return r;
}

// ---------------- weight permute: [o][ci][kh][kw] -> [(khw*256+ci)][o] ----------------
// Writes the __device__ global directly — device symbols must never be passed
// as kernel arguments from host code (host shadow symbol != device ptr).
__global__ __launch_bounds__(256) void permw_kernel(const float* __restrict__ Wm) {
    int i = blockIdx.x * 256 + threadIdx.x;       // over KC*EE
    if (i < KC * EE) {
        int o = i & 255;
        int kk = i >> 8;          // (khw)*256 + ci
        int ci = kk & 255;
        int khw = kk >> 8;
        g_wp[kk * 256 + o] = Wm[o * KC + ci * 9 + khw];
    }
}

// ---------------- enorm3: static-smem staged, serial ascending per row ----------------
#define LN_STR 260
__global__ __launch_bounds__(256) void enorm3_kernel(const float* __restrict__ cb) {
    __shared__ float ls[32 * LN_STR];              // 33.3 KB static
    int t = threadIdx.x;
    int r0 = blockIdx.x * 32;
    const float4* src = (const float4*)(cb + r0 * 256);
    #pragma unroll
    for (int e = 0; e < 8; e++) {
        int lin = t + (e << 8);                    // 0..2047
        float4 v = src[lin];
        int row = lin >> 6;
        int kq = (lin & 63) << 2;
        *(float4*)&ls[row * LN_STR + kq] = v;
    }
    __syncthreads();
    if (t < 32) {
        const float* x = ls + t * LN_STR;
        float s = 0.f;
        for (int k = 0; k < 256; k++)
            s = __fadd_rn(s, __fmul_rn(x[k], x[k]));
        g_enorm[r0 + t] = s;
    }
}

// ---------------- conv1: bit-exact serial-k im2col GEMM ----------------
__global__ __launch_bounds__(256, 2) void conv1_exact(const float* __restrict__ X,
                                                      const float* __restrict__ bias) {
    __shared__ float As[16][132];
    __shared__ float Bs[16][132];

    int t = threadIdx.x;
    int tx = t & 15, ty = t >> 4;
    int row0 = blockIdx.x * 128;
    int n0 = blockIdx.y * 128;

    float acc[8][8];
    #pragma unroll
    for (int i = 0; i < 8; i++)
        #pragma unroll
        for (int j = 0; j < 8; j++) acc[i][j] = 0.f;

    for (int k0 = 0; k0 < KC; k0 += 16) {
        #pragma unroll
        for (int e = 0; e < 8; e++) {
            int lin = t + e * 256;
            int m = lin & 127, k = lin >> 7;
            int kk = k0 + k;
            int ci = kk & 255;
            int khw = kk >> 8;
            int kh = khw / 3, kw = khw - kh * 3;
            int row = row0 + m;
            int b = row >> 10;
            int hw = row & 1023;
            int h = (hw >> 5) + kh - 1;
            int w = (hw & 31) + kw - 1;
            float v = 0.f;
            if ((unsigned)h < 32u && (unsigned)w < 32u)
                v = X[((b * 256 + ci) << 10) + (h << 5) + w];
            As[k][m] = v;
            Bs[k][m] = g_wp[(k0 + k) * 256 + n0 + m];
        }
        __syncthreads();
        #pragma unroll
        for (int k = 0; k < 16; k++) {
            float a[8], b2[8];
            #pragma unroll
            for (int i = 0; i < 8; i++) a[i] = As[k][ty * 8 + i];
            #pragma unroll
            for (int j = 0; j < 8; j++) b2[j] = Bs[k][tx * 8 + j];
            #pragma unroll
            for (int i = 0; i < 8; i++)
                #pragma unroll
                for (int j = 0; j < 8; j++)
                    acc[i][j] = __fmaf_rn(a[i], b2[j], acc[i][j]);
        }
        __syncthreads();
    }

    #pragma unroll
    for (int i = 0; i < 8; i++) {
        int row = row0 + ty * 8 + i;
        #pragma unroll
        for (int j = 0; j < 8; j++) {
            int n = n0 + tx * 8 + j;
            g_ze[row * 256 + n] = __fadd_rn(acc[i][j], bias[n]);
        }
    }
}

// ---------------- ln3: static-smem staged, serial-scalar per row ----------------
__global__ __launch_bounds__(256) void ln3_kernel(const float* __restrict__ g,
                                                  const float* __restrict__ be) {
    __shared__ float ls[32 * LN_STR];              // 33.3 KB static
    __shared__ float gg[256], bb[256];
    int t = threadIdx.x;
    int r0 = blockIdx.x * 32;
    gg[t] = g[t];
    bb[t] = be[t];
    const float4* src = (const float4*)(g_ze + r0 * 256);
    #pragma unroll
    for (int e = 0; e < 8; e++) {
        int lin = t + (e << 8);
        float4 v = src[lin];
        int row = lin >> 6;
        int kq = (lin & 63) << 2;
        *(float4*)&ls[row * LN_STR + kq] = v;
    }
    __syncthreads();
    if (t < 32) {
        float* x = ls + t * LN_STR;
        float s = 0.f;
        for (int k = 0; k < 256; k++) s = __fadd_rn(s, x[k]);
        float mu = __fmul_rn(s, 1.f / 256.f);
        float s2 = 0.f;
        for (int k = 0; k < 256; k++) {
            float tq = __fsub_rn(x[k], mu);
            s2 = __fadd_rn(s2, __fmul_rn(tq, tq));
        }
        float var = __fmul_rn(s2, 1.f / 256.f);
        float rs = __fdiv_rn(1.0f, __fsqrt_rn(__fadd_rn(var, 1e-5f)));
        float zn = 0.f;
        for (int k = 0; k < 256; k++) {
            float tq = __fsub_rn(x[k], mu);
            float a = __fmul_rn(tq, rs);
            float v = __fadd_rn(__fmul_rn(a, gg[k]), bb[k]);
            x[k] = v;                                    // in-place
            zn = __fadd_rn(zn, __fmul_rn(v, v));
        }
        g_znorm[r0 + t] = zn;
    }
    __syncthreads();
    float4* dst = (float4*)(g_zf + r0 * 256);
    #pragma unroll
    for (int e = 0; e < 8; e++) {
        int lin = t + (e << 8);
        int row = lin >> 6;
        int kq = (lin & 63) << 2;
        dst[lin] = *(const float4*)&ls[row * LN_STR + kq];
    }
}

// ---------------- dist_v5: 128x128 tiles, split-n, candidates to global ----------------
// d_n = RN( RN(znorm + enorm_n) - 2*dot_n ), dot = serial ascending fma over k.
// grid (128, 2): blockIdx.y selects codebook half [by*4096, by*4096+4096).
// Per-thread candidates (n ascending, strict <) -> g_cv/g_ci; merged exactly later.
__global__ __launch_bounds__(256, 2) void dist_v5(const float* __restrict__ cb) {
    __shared__ float As[16][132];
    __shared__ float Bs[16][132];
    __shared__ float zns[128];

    int t = threadIdx.x;
    int tx = t & 15, ty = t >> 4;
    int row0 = blockIdx.x * 128;
    int nbase = blockIdx.y * 4096;

    if (t < 128) zns[t] = g_znorm[row0 + t];
    __syncthreads();

    float best[8];
    int bidx[8];
    #pragma unroll
    for (int i = 0; i < 8; i++) { best[i] = CUDART_INF_F; bidx[i] = 0x7fffffff; }

    #pragma unroll 1
    for (int nt = 0; nt < 32; nt++) {
        int n0 = nbase + nt * 128;

        float acc[8][8];
        #pragma unroll
        for (int i = 0; i < 8; i++)
            #pragma unroll
            for (int j = 0; j < 8; j++) acc[i][j] = 0.f;

        #pragma unroll 1
        for (int k0 = 0; k0 < 256; k0 += 16) {
            // A: [k][m] from zf — consecutive t -> consecutive k -> coalesced
            #pragma unroll
            for (int e = 0; e < 8; e++) {
                int lin = t + e * 256;
                int k = lin & 15, m = lin >> 4;
                As[k][m] = g_zf[(row0 + m) * 256 + k0 + k];
            }
            // B: [k][n] from cb — same mapping, coalesced
            #pragma unroll
            for (int e = 0; e < 8; e++) {
                int lin = t + e * 256;
                int k = lin & 15, n = lin >> 4;
                Bs[k][n] = cb[(n0 + n) * 256 + k0 + k];
            }
            __syncthreads();
            #pragma unroll
            for (int k = 0; k < 16; k++) {           // k ascending: serial fma chain
                float a[8], b2[8];
                #pragma unroll
                for (int i = 0; i < 8; i++) a[i] = As[k][ty * 8 + i];
                #pragma unroll
                for (int j = 0; j < 8; j++) b2[j] = Bs[k][tx * 8 + j];
                #pragma unroll
                for (int i = 0; i < 8; i++)
                    #pragma unroll
                    for (int j = 0; j < 8; j++)
                        acc[i][j] = __fmaf_rn(a[i], b2[j], acc[i][j]);
            }
            __syncthreads();
        }

        // argmin epilogue: n ascending within thread; strict < keeps lowest index
        #pragma unroll
        for (int j = 0; j < 8; j++) {
            int n = n0 + tx * 8 + j;
            float en = g_enorm[n];
            #pragma unroll
            for (int i = 0; i < 8; i++) {
                float S = __fadd_rn(zns[ty * 8 + i], en);
                float d = __fsub_rn(S, __fmul_rn(2.0f, acc[i][j]));
                if (d < best[i]) { best[i] = d; bidx[i] = n; }
            }
        }
    }

    // write per-thread candidates: cand id = by*16 + tx, one per (cand,row)
    int c = blockIdx.y * 16 + tx;
    #pragma unroll
    for (int i = 0; i < 8; i++) {
        int row = row0 + ty * 8 + i;
        g_cv[c * ROWS + row] = best[i];
        g_ci[c * ROWS + row] = bidx[i];
    }
}

// ---------------- argmin merge: exact lowest-index-tie reduction over 32 candidates ----------------
__global__ __launch_bounds__(256) void argmin_merge() {
    int row = blockIdx.x * 256 + threadIdx.x;      // 64 blocks x 256
    float bv = g_cv[row];
    int bi = g_ci[row];
    #pragma unroll 4
    for (int c = 1; c < 32; c++) {
        float v = g_cv[c * ROWS + row];
        int i = g_ci[c * ROWS + row];
        if (v < bv || (v == bv && i < bi)) { bv = v; bi = i; }
    }
    g_idx[row] = bi;
}

// ---------------- gather2: coalesced straight-through + loss partials ----------------
__global__ __launch_bounds__(256) void gather2_kernel(const float* __restrict__ cb) {
    __shared__ float sq[256][33];
    __shared__ int sid[32];
    __shared__ float sh[32];
    int t = threadIdx.x;
    int r0 = blockIdx.x * 32;
    if (t < 32) sid[t] = g_idx[r0 + t];
    __syncthreads();
    float local = 0.f;
    #pragma unroll 4
    for (int i = 0; i < 32; i++) {
        float e = cb[sid[i] * 256 + t];
        float z = g_ze[(r0 + i) * 256 + t];
        float d = __fsub_rn(e, z);
        sq[t][i] = __fadd_rn(z, d);              // straight-through bits
        local += d * d;                          // scalar loss: tolerance ok
    }
    __syncthreads();
    int b = r0 >> 10, hw0 = r0 & 1023;
    int w = t >> 5, lane = t & 31;
    #pragma unroll 4
    for (int eb = 0; eb < 32; eb++) {
        int e = eb * 8 + w;
        g_zq[((b * 256 + e) << 10) + hw0 + lane] = sq[e][lane];
    }
    float s = blk_sum(local, sh);
    if (t == 0) g_lpart[blockIdx.x] = s;
}

// ---------------- conv2 ----------------
__global__ __launch_bounds__(256, 2) void conv2_gemm(const float* __restrict__ Wm,
                                                     const float* __restrict__ bias,
                                                     float* __restrict__ outNCHW) {
    __shared__ float As[16][132];
    __shared__ float Bs[16][132];
    int t = threadIdx.x;
    int tx = t & 15, ty = t >> 4;
    int row0 = blockIdx.x * 128;
    int n0 = blockIdx.y * 128;

    float acc[8][8];
    #pragma unroll
    for (int i = 0; i < 8; i++)
        #pragma unroll
        for (int j = 0; j < 8; j++) acc[i][j] = 0.f;

    for (int k0 = 0; k0 < KC; k0 += 16) {
        #pragma unroll
        for (int e = 0; e < 8; e++) {
            int lin = t + e * 256;
            int m = lin & 127, k = lin >> 7;
            int kk = k0 + k;
            int ci = kk / 9;
            int r9 = kk - ci * 9;
            int kh = r9 / 3, kw = r9 - kh * 3;
            int row = row0 + m;
            int b = row >> 10;
            int hw = row & 1023;
            int h = (hw >> 5) + kh - 1;
            int w = (hw & 31) + kw - 1;
            float v = 0.f;
            if ((unsigned)h < 32u && (unsigned)w < 32u)
                v = g_zq[((b * 256 + ci) << 10) + (h << 5) + w];
            As[k][m] = v;
        }
        #pragma unroll
        for (int e = 0; e < 8; e++) {
            int lin = t + e * 256;
            int k = lin & 15, n = lin >> 4;
            Bs[k][n] = Wm[(n0 + n) * KC + k0 + k];
        }
        __syncthreads();
        #pragma unroll
        for (int k = 0; k < 16; k++) {
            float a[8], b2[8];
            #pragma unroll
            for (int i = 0; i < 8; i++) a[i] = As[k][ty * 8 + i];
            #pragma unroll
            for (int j = 0; j < 8; j++) b2[j] = Bs[k][tx * 8 + j];
            #pragma unroll
            for (int i = 0; i < 8; i++)
                #pragma unroll
                for (int j = 0; j < 8; j++)
                    acc[i][j] = __fmaf_rn(a[i], b2[j], acc[i][j]);
        }
        __syncthreads();
    }

    #pragma unroll
    for (int i = 0; i < 8; i++) {
        int row = row0 + ty * 8 + i;
        int b = row >> 10;
        int hw = row & 1023;
        #pragma unroll
        for (int j = 0; j < 8; j++) {
            int n = n0 + tx * 8 + j;
            outNCHW[((b * 256 + n) << 10) + hw] = __fadd_rn(acc[i][j], bias[n]);
        }
    }
}

// ---------------- finalize: loss + idx ----------------
__global__ __launch_bounds__(256) void finalize_kernel(float* __restrict__ out, int out_size) {
    __shared__ float sh[32];
    int gidx = blockIdx.x * blockDim.x + threadIdx.x;
    if (gidx < ROWS && IDX_OFF + gidx < out_size)
        out[IDX_OFF + gidx] = (float)g_idx[gidx];
    if (blockIdx.x == 0) {
        float s = 0.f;
        for (int k = threadIdx.x; k < GBLK; k += 256) s += g_lpart[k];
        float tot = blk_sum(s, sh);
        if (threadIdx.x == 0 && LOSS_OFF < out_size)
            out[LOSS_OFF] = 1.25f * tot / (float)OUT_ELEMS;
    }
}

// ---------------- launcher ----------------
extern "C" void kernel_launch(void* const* d_in, const int* in_sizes, int n_in,
                              void* d_out, int out_size) {
    (void)in_sizes; (void)n_in;
    const float* z       = (const float*)d_in[0];
    const float* emb_w   = (const float*)d_in[1];
    const float* emb_b   = (const float*)d_in[2];
    const float* ln_g    = (const float*)d_in[3];
    const float* ln_b    = (const float*)d_in[4];
    const float* cb      = (const float*)d_in[5];
    const float* unemb_w = (const float*)d_in[6];
    const float* unemb_b = (const float*)d_in[7];
    float* out = (float*)d_out;

    permw_kernel<<<(KC * EE + 255) / 256, 256>>>(emb_w);
    enorm3_kernel<<<NE / 32, 256>>>(cb);
    conv1_exact<<<dim3(ROWS / 128, 2), 256>>>(z, emb_b);                  // -> g_ze
    ln3_kernel<<<ROWS / 32, 256>>>(ln_g, ln_b);                           // -> g_zf, g_znorm
    dist_v5<<<dim3(ROWS / 128, 2), 256>>>(cb);                            // -> g_cv/g_ci
    argmin_merge<<<ROWS / 256, 256>>>();                                  // -> g_idx
    gather2_kernel<<<GBLK, 256>>>(cb);                                    // -> g_zq, g_lpart
    conv2_gemm<<<dim3(ROWS / 128, 2), 256>>>(unemb_w, unemb_b, out);      // -> out
    finalize_kernel<<<ROWS / 256, 256>>>(out, out_size);
}